// round 15
// baseline (speedup 1.0000x reference)
#include <cuda_runtime.h>
#include <cstdint>

#define D_MODEL 1024
#define KV_DIM  256
#define L_SEQ   4096
#define HD      64
#define NHEADS  16

// Scratch (device globals; no allocations allowed)
__device__ float g_X32 [L_SEQ * D_MODEL];
__device__ float g_Wq32[D_MODEL * D_MODEL];
__device__ float g_Wk32[D_MODEL * KV_DIM];
__device__ float g_Wv32[D_MODEL * KV_DIM];
__device__ float g_Wo32[D_MODEL * D_MODEL];
__device__ float g_Q [L_SEQ * D_MODEL];   // rounded + pre-scaled by QSCALE
__device__ float g_K [L_SEQ * KV_DIM];    // rounded, row-major
__device__ float g_V [L_SEQ * KV_DIM];    // rounded
__device__ float g_A [L_SEQ * D_MODEL];   // attention out, rounded

// 0.125 * log2(e): folds 1/sqrt(64) AND exp->exp2
#define QSCALE 0.18033688011112042f

__device__ __forceinline__ uint32_t to_tf32(float x) {
    uint32_t y;
    asm("cvt.rna.tf32.f32 %0, %1;" : "=r"(y) : "f"(x));
    return y;
}
__device__ __forceinline__ float to_tf32f(float x) { return __uint_as_float(to_tf32(x)); }

__device__ __forceinline__ float ex2(float x) {
    float y;
    asm("ex2.approx.f32 %0, %1;" : "=f"(y) : "f"(x));
    return y;
}

__device__ __forceinline__ void mma_tf32(float c[4], const uint32_t a[4], const uint32_t b[2]) {
    asm volatile("mma.sync.aligned.m16n8k8.row.col.f32.tf32.tf32.f32 "
        "{%0,%1,%2,%3},{%4,%5,%6,%7},{%8,%9},{%0,%1,%2,%3};"
        : "+f"(c[0]), "+f"(c[1]), "+f"(c[2]), "+f"(c[3])
        : "r"(a[0]), "r"(a[1]), "r"(a[2]), "r"(a[3]), "r"(b[0]), "r"(b[1]));
}

__device__ __forceinline__ void cp16(void* smem, const void* gmem) {
    uint32_t s = (uint32_t)__cvta_generic_to_shared(smem);
    asm volatile("cp.async.cg.shared.global [%0], [%1], 16;" :: "r"(s), "l"(gmem));
}
#define CP_COMMIT() asm volatile("cp.async.commit_group;")
#define CP_WAIT1()  asm volatile("cp.async.wait_group 1;")
#define CP_WAIT0()  asm volatile("cp.async.wait_group 0;")

// Dynamic smem sizes
#define GEMM_SMEM_BYTES  (3 * (128*20 + 16*136) * 4)            // 56832
#define ATTN_SMEM_BYTES  ((2*32*68 + 2*32*72 + 2*64*36) * 4)    // 54272

// ---------------------------------------------------------------------------
// Fused prep: tf32-round x, Wq, Wk, Wv, Wo
// ---------------------------------------------------------------------------
#define SEG_X  (L_SEQ*D_MODEL/4)
#define SEG_WQ (D_MODEL*D_MODEL/4)
#define SEG_WK (D_MODEL*KV_DIM/4)
#define PREP_TOTAL (SEG_X + 2*SEG_WQ + 2*SEG_WK)

__global__ __launch_bounds__(256) void prep_round_all(
    const float* __restrict__ x,  const float* __restrict__ Wq,
    const float* __restrict__ Wk, const float* __restrict__ Wv,
    const float* __restrict__ Wo)
{
    int i = blockIdx.x * blockDim.x + threadIdx.x;
    if (i >= PREP_TOTAL) return;
    const float* src; float* dst; int off;
    if (i < SEG_X)                         { src = x;  dst = g_X32;  off = i; }
    else if (i < SEG_X + SEG_WQ)           { src = Wq; dst = g_Wq32; off = i - SEG_X; }
    else if (i < SEG_X + SEG_WQ + SEG_WK)  { src = Wk; dst = g_Wk32; off = i - SEG_X - SEG_WQ; }
    else if (i < SEG_X + SEG_WQ + 2*SEG_WK){ src = Wv; dst = g_Wv32; off = i - SEG_X - SEG_WQ - SEG_WK; }
    else                                   { src = Wo; dst = g_Wo32; off = i - SEG_X - SEG_WQ - 2*SEG_WK; }
    float4 v = ((const float4*)src)[off];
    v.x = to_tf32f(v.x); v.y = to_tf32f(v.y);
    v.z = to_tf32f(v.z); v.w = to_tf32f(v.w);
    ((float4*)dst)[off] = v;
}

// ---------------------------------------------------------------------------
// tf32 GEMM. Block 128x128, 256 thr = 8 warps (2m x 4n), warp tile 64x32.
// 3-stage cp.async pipeline (dynamic smem), ONE barrier per k-step.
// MODE: 0 plain out; 1 rounded; 2 rounded*QSCALE (for Q).
// ---------------------------------------------------------------------------
template<int MODE>
__device__ __forceinline__ void gemm_body(
    const float* __restrict__ A, const float* __restrict__ B,
    const float* __restrict__ bias, float* __restrict__ C,
    int N, int K, int row0, int col0)
{
    extern __shared__ char sm[];
    auto As = reinterpret_cast<float(*)[128][20]>(sm);
    auto Bs = reinterpret_cast<float(*)[16][136]>(sm + 3 * 128 * 20 * 4);

    const int tid = threadIdx.x;
    const int lane = tid & 31, wid = tid >> 5;
    const int wm = wid >> 2, wn = wid & 3;
    const int lr = lane >> 2, lc = lane & 3;

    auto load_stage = [&](int buf, int k0) {
        #pragma unroll
        for (int i = 0; i < 2; i++) {               // A: 128 rows x 4 float4
            int u = tid + i * 256;
            int r = u >> 2, o = (u & 3) * 4;
            cp16(&As[buf][r][o], &A[(row0 + r) * K + k0 + o]);
        }
        #pragma unroll
        for (int i = 0; i < 2; i++) {               // B: 16 rows x 32 float4
            int u = tid + i * 256;
            int kk = u >> 5, o = (u & 31) * 4;
            cp16(&Bs[buf][kk][o], &B[(k0 + kk) * N + col0 + o]);
        }
    };

    const int NT = K / 16;
    float acc[4][4][4] = {};
    load_stage(0, 0);  CP_COMMIT();
    load_stage(1, 16); CP_COMMIT();

    for (int t = 0; t < NT; t++) {
        int buf = t % 3;
        CP_WAIT1();            // group t landed (t+1 may be in flight)
        __syncthreads();       // also protects buf (t+2)%3 from early overwrite
        if (t + 2 < NT) load_stage((t + 2) % 3, (t + 2) * 16);
        CP_COMMIT();           // always commit -> uniform group FIFO

        #pragma unroll
        for (int ks = 0; ks < 2; ks++) {
            uint32_t a[4][4], b[4][2];
            #pragma unroll
            for (int mi = 0; mi < 4; mi++) {
                int m0 = wm * 64 + mi * 16;
                a[mi][0] = __float_as_uint(As[buf][m0 + lr    ][ks*8 + lc    ]);
                a[mi][1] = __float_as_uint(As[buf][m0 + lr + 8][ks*8 + lc    ]);
                a[mi][2] = __float_as_uint(As[buf][m0 + lr    ][ks*8 + lc + 4]);
                a[mi][3] = __float_as_uint(As[buf][m0 + lr + 8][ks*8 + lc + 4]);
            }
            #pragma unroll
            for (int ni = 0; ni < 4; ni++) {
                int n0 = wn * 32 + ni * 8;
                b[ni][0] = __float_as_uint(Bs[buf][ks*8 + lc    ][n0 + lr]);
                b[ni][1] = __float_as_uint(Bs[buf][ks*8 + lc + 4][n0 + lr]);
            }
            #pragma unroll
            for (int mi = 0; mi < 4; mi++)
                #pragma unroll
                for (int ni = 0; ni < 4; ni++)
                    mma_tf32(acc[mi][ni], a[mi], b[ni]);
        }
    }

    #pragma unroll
    for (int mi = 0; mi < 4; mi++) {
        #pragma unroll
        for (int ni = 0; ni < 4; ni++) {
            int r = row0 + wm*64 + mi*16 + lr;
            int c = col0 + wn*32 + ni*8 + 2*lc;
            float v00 = acc[mi][ni][0] + bias[c];
            float v01 = acc[mi][ni][1] + bias[c+1];
            float v10 = acc[mi][ni][2] + bias[c];
            float v11 = acc[mi][ni][3] + bias[c+1];
            if (MODE == 0) {
                C[r*N + c] = v00;        C[r*N + c + 1] = v01;
                C[(r+8)*N + c] = v10;    C[(r+8)*N + c + 1] = v11;
            } else if (MODE == 1) {
                C[r*N + c] = to_tf32f(v00);        C[r*N + c + 1] = to_tf32f(v01);
                C[(r+8)*N + c] = to_tf32f(v10);    C[(r+8)*N + c + 1] = to_tf32f(v11);
            } else {
                C[r*N + c] = to_tf32f(v00 * QSCALE);        C[r*N + c + 1] = to_tf32f(v01 * QSCALE);
                C[(r+8)*N + c] = to_tf32f(v10 * QSCALE);    C[(r+8)*N + c + 1] = to_tf32f(v11 * QSCALE);
            }
        }
    }
}

template<int MODE>
__global__ __launch_bounds__(256) void gemm_tf32(
    const float* __restrict__ A, const float* __restrict__ B,
    const float* __restrict__ bias, float* __restrict__ C,
    int N, int K)
{
    gemm_body<MODE>(A, B, bias, C, N, K, blockIdx.y * 128, blockIdx.x * 128);
}

// Fused K+V projection: grid.x 0..3 covers 2x256 cols; <2 -> K, >=2 -> V.
__global__ __launch_bounds__(256) void gemm_kv(
    const float* __restrict__ A,
    const float* __restrict__ Wk, const float* __restrict__ bk,
    const float* __restrict__ Wv, const float* __restrict__ bv,
    int K)
{
    int bx = blockIdx.x;
    const float* B; const float* bias; float* C;
    if (bx < 2) { B = Wk; bias = bk; C = g_K; }
    else        { B = Wv; bias = bv; C = g_V; bx -= 2; }
    gemm_body<1>(A, B, bias, C, KV_DIM, K, blockIdx.y * 128, bx * 128);
}

// ---------------------------------------------------------------------------
// Flash attention, tf32 mma, no online softmax.  Cross-tile exp pipelining:
// iteration i computes S_i, exps it (MUFU latency hidden under the PV_{i-1}
// mma stream), runs PV_{i-1} from double-buffered Ps, stages P_i, then
// prefetches tile i+1.  Accumulation order identical to the R8/R12 kernel.
// grid = (64 q-tiles, 16 heads), 128 threads = 4 warps; warp owns 16 q-rows.
// Dynamic smem: Ks 2x32x68 | Vs 2x32x72 | Ps 2x64x36  (54272 B, 4 CTAs/SM).
// ---------------------------------------------------------------------------
#define NTILES (L_SEQ / 32)

__global__ __launch_bounds__(128, 4) void gqa_attn_tf32()
{
    extern __shared__ char sm[];
    auto Ks = reinterpret_cast<float(*)[32][68]>(sm);
    auto Vs = reinterpret_cast<float(*)[32][72]>(sm + 2*32*68*4);
    auto Ps = reinterpret_cast<float(*)[64][36]>(sm + 2*32*68*4 + 2*32*72*4);

    const int head = blockIdx.y, kvh = head >> 2;
    const int q0 = blockIdx.x * 64;
    const int tid = threadIdx.x;
    const int lane = tid & 31, wid = tid >> 5;
    const int lr = lane >> 2, lc = lane & 3;
    const int m_base = wid * 16;

    auto load_tile = [&](int k0, int buf) {
        #pragma unroll
        for (int i = 0; i < 4; i++) {
            int u = tid + i * 128;
            int key = u >> 4, o = (u & 15) * 4;
            cp16(&Ks[buf][key][o], &g_K[(k0 + key) * KV_DIM + kvh*HD + o]);
            cp16(&Vs[buf][key][o], &g_V[(k0 + key) * KV_DIM + kvh*HD + o]);
        }
    };

    // Q fragments (pre-scaled by QSCALE, pre-rounded)
    uint32_t qa[8][4];
    {
        const float* Qb = g_Q + (q0 + m_base) * D_MODEL + head * HD;
        #pragma unroll
        for (int ks = 0; ks < 8; ks++) {
            qa[ks][0] = __float_as_uint(Qb[(lr    )*D_MODEL + ks*8 + lc    ]);
            qa[ks][1] = __float_as_uint(Qb[(lr + 8)*D_MODEL + ks*8 + lc    ]);
            qa[ks][2] = __float_as_uint(Qb[(lr    )*D_MODEL + ks*8 + lc + 4]);
            qa[ks][3] = __float_as_uint(Qb[(lr + 8)*D_MODEL + ks*8 + lc + 4]);
        }
    }

    float o[8][4] = {};         // persistent PV accumulators (never rescaled)
    float lacc0 = 0.f, lacc1 = 0.f;

    load_tile(0, 0);
    CP_COMMIT();

    for (int i = 0; i < NTILES; i++) {
        const int b = i & 1;    // tile i in buf b; P_i staged to Ps[b]
        CP_WAIT0();
        __syncthreads();        // tile i visible to all warps

        // S_i = Q @ K_i^T  (16 x 32 per warp)
        float s[4][4] = {};
        #pragma unroll
        for (int ks = 0; ks < 8; ks++) {
            uint32_t bb[4][2];
            #pragma unroll
            for (int nt = 0; nt < 4; nt++) {
                bb[nt][0] = __float_as_uint(Ks[b][nt*8 + lr][ks*8 + lc    ]);
                bb[nt][1] = __float_as_uint(Ks[b][nt*8 + lr][ks*8 + lc + 4]);
            }
            #pragma unroll
            for (int nt = 0; nt < 4; nt++)
                mma_tf32(s[nt], qa[ks], bb[nt]);
        }

        // exp in place (MUFU results consumed only by the STS below,
        // which sits after the PV_{i-1} mma stream -> latency hidden)
        #pragma unroll
        for (int nt = 0; nt < 4; nt++) {
            s[nt][0] = ex2(s[nt][0]);
            s[nt][1] = ex2(s[nt][1]);
            s[nt][2] = ex2(s[nt][2]);
            s[nt][3] = ex2(s[nt][3]);
            lacc0 += s[nt][0] + s[nt][1];
            lacc1 += s[nt][2] + s[nt][3];
        }

        // PV_{i-1}: o += P_{i-1} @ V_{i-1}  (buffers b^1)
        if (i > 0) {
            #pragma unroll
            for (int ks = 0; ks < 4; ks++) {
                uint32_t a[4];
                a[0] = __float_as_uint(Ps[b^1][m_base + lr    ][ks*8 + lc    ]);
                a[1] = __float_as_uint(Ps[b^1][m_base + lr + 8][ks*8 + lc    ]);
                a[2] = __float_as_uint(Ps[b^1][m_base + lr    ][ks*8 + lc + 4]);
                a[3] = __float_as_uint(Ps[b^1][m_base + lr + 8][ks*8 + lc + 4]);
                #pragma unroll
                for (int nt = 0; nt < 8; nt++) {
                    uint32_t bb[2];
                    bb[0] = __float_as_uint(Vs[b^1][ks*8 + lc    ][nt*8 + lr]);
                    bb[1] = __float_as_uint(Vs[b^1][ks*8 + lc + 4][nt*8 + lr]);
                    mma_tf32(o[nt], a, bb);
                }
            }
        }

        // stage P_i (own rows; read next iteration by this warp only)
        #pragma unroll
        for (int nt = 0; nt < 4; nt++) {
            *(float2*)&Ps[b][m_base + lr    ][nt*8 + 2*lc] = make_float2(s[nt][0], s[nt][1]);
            *(float2*)&Ps[b][m_base + lr + 8][nt*8 + 2*lc] = make_float2(s[nt][2], s[nt][3]);
        }

        __syncthreads();        // all reads of buf b^1 complete
        if (i + 1 < NTILES) load_tile((i + 1) * 32, b ^ 1);
        CP_COMMIT();
    }

    // tail: PV for the last tile (i = NTILES-1, buffers 1)
    {
        #pragma unroll
        for (int ks = 0; ks < 4; ks++) {
            uint32_t a[4];
            a[0] = __float_as_uint(Ps[1][m_base + lr    ][ks*8 + lc    ]);
            a[1] = __float_as_uint(Ps[1][m_base + lr + 8][ks*8 + lc    ]);
            a[2] = __float_as_uint(Ps[1][m_base + lr    ][ks*8 + lc + 4]);
            a[3] = __float_as_uint(Ps[1][m_base + lr + 8][ks*8 + lc + 4]);
            #pragma unroll
            for (int nt = 0; nt < 8; nt++) {
                uint32_t bb[2];
                bb[0] = __float_as_uint(Vs[1][ks*8 + lc    ][nt*8 + lr]);
                bb[1] = __float_as_uint(Vs[1][ks*8 + lc + 4][nt*8 + lr]);
                mma_tf32(o[nt], a, bb);
            }
        }
    }

    // Reduce l across the 4 lanes of each row, normalize, write out
    lacc0 += __shfl_xor_sync(~0u, lacc0, 1); lacc0 += __shfl_xor_sync(~0u, lacc0, 2);
    lacc1 += __shfl_xor_sync(~0u, lacc1, 1); lacc1 += __shfl_xor_sync(~0u, lacc1, 2);
    float inv0 = 1.f / lacc0, inv1 = 1.f / lacc1;
    float* Ob = g_A + (q0 + m_base) * D_MODEL + head * HD;
    #pragma unroll
    for (int nt = 0; nt < 8; nt++) {
        Ob[(lr    )*D_MODEL + nt*8 + 2*lc    ] = to_tf32f(o[nt][0] * inv0);
        Ob[(lr    )*D_MODEL + nt*8 + 2*lc + 1] = to_tf32f(o[nt][1] * inv0);
        Ob[(lr + 8)*D_MODEL + nt*8 + 2*lc    ] = to_tf32f(o[nt][2] * inv1);
        Ob[(lr + 8)*D_MODEL + nt*8 + 2*lc + 1] = to_tf32f(o[nt][3] * inv1);
    }
}

// ---------------------------------------------------------------------------
extern "C" void kernel_launch(void* const* d_in, const int* in_sizes, int n_in,
                              void* d_out, int out_size)
{
    const float* x  = (const float*)d_in[0];
    const float* Wq = (const float*)d_in[1];
    const float* bq = (const float*)d_in[2];
    const float* Wk = (const float*)d_in[3];
    const float* bk = (const float*)d_in[4];
    const float* Wv = (const float*)d_in[5];
    const float* bv = (const float*)d_in[6];
    const float* Wo = (const float*)d_in[7];
    const float* bo = (const float*)d_in[8];
    float* out = (float*)d_out;

    float *X32, *Wq32, *Wk32, *Wv32, *Wo32, *Qp, *Ap;
    cudaGetSymbolAddress((void**)&X32,  g_X32);
    cudaGetSymbolAddress((void**)&Wq32, g_Wq32);
    cudaGetSymbolAddress((void**)&Wk32, g_Wk32);
    cudaGetSymbolAddress((void**)&Wv32, g_Wv32);
    cudaGetSymbolAddress((void**)&Wo32, g_Wo32);
    cudaGetSymbolAddress((void**)&Qp,   g_Q);
    cudaGetSymbolAddress((void**)&Ap,   g_A);

    // Opt in to >48KB dynamic shared memory (idempotent, host-side)
    cudaFuncSetAttribute(gemm_tf32<0>, cudaFuncAttributeMaxDynamicSharedMemorySize, GEMM_SMEM_BYTES);
    cudaFuncSetAttribute(gemm_tf32<2>, cudaFuncAttributeMaxDynamicSharedMemorySize, GEMM_SMEM_BYTES);
    cudaFuncSetAttribute(gemm_kv,      cudaFuncAttributeMaxDynamicSharedMemorySize, GEMM_SMEM_BYTES);
    cudaFuncSetAttribute(gqa_attn_tf32, cudaFuncAttributeMaxDynamicSharedMemorySize, ATTN_SMEM_BYTES);

    // Prep: one fused tf32-rounding pass
    prep_round_all<<<(PREP_TOTAL + 255)/256, 256>>>(x, Wq, Wk, Wv, Wo);

    // Projections
    gemm_tf32<2><<<dim3(D_MODEL/128, L_SEQ/128), 256, GEMM_SMEM_BYTES>>>(X32, Wq32, bq, Qp, D_MODEL, D_MODEL);
    gemm_kv    <<<dim3(4,            L_SEQ/128), 256, GEMM_SMEM_BYTES>>>(X32, Wk32, bk, Wv32, bv, D_MODEL);
    // Attention (exp-pipelined)
    gqa_attn_tf32<<<dim3(L_SEQ/64, NHEADS), 128, ATTN_SMEM_BYTES>>>();
    // Output projection
    gemm_tf32<0><<<dim3(D_MODEL/128, L_SEQ/128), 256, GEMM_SMEM_BYTES>>>(Ap, Wo32, bo, out, D_MODEL, D_MODEL);
}

// round 16
// speedup vs baseline: 1.0009x; 1.0009x over previous
#include <cuda_runtime.h>
#include <cstdint>

#define D_MODEL 1024
#define KV_DIM  256
#define L_SEQ   4096
#define HD      64
#define NHEADS  16

// Scratch (device globals; no allocations allowed)
__device__ float g_X32 [L_SEQ * D_MODEL];
__device__ float g_Wq32[D_MODEL * D_MODEL];
__device__ float g_Wk32[D_MODEL * KV_DIM];
__device__ float g_Wv32[D_MODEL * KV_DIM];
__device__ float g_Wo32[D_MODEL * D_MODEL];
__device__ float g_Q [L_SEQ * D_MODEL];   // rounded + pre-scaled by QSCALE
__device__ float g_K [L_SEQ * KV_DIM];    // rounded, row-major
__device__ float g_V [L_SEQ * KV_DIM];    // rounded
__device__ float g_A [L_SEQ * D_MODEL];   // attention out, rounded

// 0.125 * log2(e): folds 1/sqrt(64) AND exp->exp2
#define QSCALE 0.18033688011112042f

__device__ __forceinline__ uint32_t to_tf32(float x) {
    uint32_t y;
    asm("cvt.rna.tf32.f32 %0, %1;" : "=r"(y) : "f"(x));
    return y;
}
__device__ __forceinline__ float to_tf32f(float x) { return __uint_as_float(to_tf32(x)); }

__device__ __forceinline__ float ex2(float x) {
    float y;
    asm("ex2.approx.f32 %0, %1;" : "=f"(y) : "f"(x));
    return y;
}

__device__ __forceinline__ void mma_tf32(float c[4], const uint32_t a[4], const uint32_t b[2]) {
    asm volatile("mma.sync.aligned.m16n8k8.row.col.f32.tf32.tf32.f32 "
        "{%0,%1,%2,%3},{%4,%5,%6,%7},{%8,%9},{%0,%1,%2,%3};"
        : "+f"(c[0]), "+f"(c[1]), "+f"(c[2]), "+f"(c[3])
        : "r"(a[0]), "r"(a[1]), "r"(a[2]), "r"(a[3]), "r"(b[0]), "r"(b[1]));
}

__device__ __forceinline__ void cp16(void* smem, const void* gmem) {
    uint32_t s = (uint32_t)__cvta_generic_to_shared(smem);
    asm volatile("cp.async.cg.shared.global [%0], [%1], 16;" :: "r"(s), "l"(gmem));
}
#define CP_COMMIT() asm volatile("cp.async.commit_group;")
#define CP_WAIT1()  asm volatile("cp.async.wait_group 1;")
#define CP_WAIT0()  asm volatile("cp.async.wait_group 0;")

// Dynamic smem sizes
#define GEMM_SMEM_BYTES  (3 * (128*20 + 16*136) * 4)            // 56832
#define ATTN_SMEM_BYTES  ((2*32*68 + 2*32*72 + 2*64*36) * 4)    // 54272

// ---------------------------------------------------------------------------
// Fused prep: tf32-round x, Wq, Wk, Wv, Wo
// ---------------------------------------------------------------------------
#define SEG_X  (L_SEQ*D_MODEL/4)
#define SEG_WQ (D_MODEL*D_MODEL/4)
#define SEG_WK (D_MODEL*KV_DIM/4)
#define PREP_TOTAL (SEG_X + 2*SEG_WQ + 2*SEG_WK)

__global__ __launch_bounds__(256) void prep_round_all(
    const float* __restrict__ x,  const float* __restrict__ Wq,
    const float* __restrict__ Wk, const float* __restrict__ Wv,
    const float* __restrict__ Wo)
{
    int i = blockIdx.x * blockDim.x + threadIdx.x;
    if (i >= PREP_TOTAL) return;
    const float* src; float* dst; int off;
    if (i < SEG_X)                         { src = x;  dst = g_X32;  off = i; }
    else if (i < SEG_X + SEG_WQ)           { src = Wq; dst = g_Wq32; off = i - SEG_X; }
    else if (i < SEG_X + SEG_WQ + SEG_WK)  { src = Wk; dst = g_Wk32; off = i - SEG_X - SEG_WQ; }
    else if (i < SEG_X + SEG_WQ + 2*SEG_WK){ src = Wv; dst = g_Wv32; off = i - SEG_X - SEG_WQ - SEG_WK; }
    else                                   { src = Wo; dst = g_Wo32; off = i - SEG_X - SEG_WQ - 2*SEG_WK; }
    float4 v = ((const float4*)src)[off];
    v.x = to_tf32f(v.x); v.y = to_tf32f(v.y);
    v.z = to_tf32f(v.z); v.w = to_tf32f(v.w);
    ((float4*)dst)[off] = v;
}

// ---------------------------------------------------------------------------
// tf32 GEMM. Block 128x128, 256 thr = 8 warps (2m x 4n), warp tile 64x32.
// 3-stage cp.async pipeline (dynamic smem), ONE barrier per k-step.
// MODE: 0 plain out; 1 rounded; 2 rounded*QSCALE (for Q).
// ---------------------------------------------------------------------------
template<int MODE>
__device__ __forceinline__ void gemm_body(
    const float* __restrict__ A, const float* __restrict__ B,
    const float* __restrict__ bias, float* __restrict__ C,
    int N, int K, int row0, int col0)
{
    extern __shared__ char sm[];
    auto As = reinterpret_cast<float(*)[128][20]>(sm);
    auto Bs = reinterpret_cast<float(*)[16][136]>(sm + 3 * 128 * 20 * 4);

    const int tid = threadIdx.x;
    const int lane = tid & 31, wid = tid >> 5;
    const int wm = wid >> 2, wn = wid & 3;
    const int lr = lane >> 2, lc = lane & 3;

    auto load_stage = [&](int buf, int k0) {
        #pragma unroll
        for (int i = 0; i < 2; i++) {               // A: 128 rows x 4 float4
            int u = tid + i * 256;
            int r = u >> 2, o = (u & 3) * 4;
            cp16(&As[buf][r][o], &A[(row0 + r) * K + k0 + o]);
        }
        #pragma unroll
        for (int i = 0; i < 2; i++) {               // B: 16 rows x 32 float4
            int u = tid + i * 256;
            int kk = u >> 5, o = (u & 31) * 4;
            cp16(&Bs[buf][kk][o], &B[(k0 + kk) * N + col0 + o]);
        }
    };

    const int NT = K / 16;
    float acc[4][4][4] = {};
    load_stage(0, 0);  CP_COMMIT();
    load_stage(1, 16); CP_COMMIT();

    for (int t = 0; t < NT; t++) {
        int buf = t % 3;
        CP_WAIT1();            // group t landed (t+1 may be in flight)
        __syncthreads();       // also protects buf (t+2)%3 from early overwrite
        if (t + 2 < NT) load_stage((t + 2) % 3, (t + 2) * 16);
        CP_COMMIT();           // always commit -> uniform group FIFO

        #pragma unroll
        for (int ks = 0; ks < 2; ks++) {
            uint32_t a[4][4], b[4][2];
            #pragma unroll
            for (int mi = 0; mi < 4; mi++) {
                int m0 = wm * 64 + mi * 16;
                a[mi][0] = __float_as_uint(As[buf][m0 + lr    ][ks*8 + lc    ]);
                a[mi][1] = __float_as_uint(As[buf][m0 + lr + 8][ks*8 + lc    ]);
                a[mi][2] = __float_as_uint(As[buf][m0 + lr    ][ks*8 + lc + 4]);
                a[mi][3] = __float_as_uint(As[buf][m0 + lr + 8][ks*8 + lc + 4]);
            }
            #pragma unroll
            for (int ni = 0; ni < 4; ni++) {
                int n0 = wn * 32 + ni * 8;
                b[ni][0] = __float_as_uint(Bs[buf][ks*8 + lc    ][n0 + lr]);
                b[ni][1] = __float_as_uint(Bs[buf][ks*8 + lc + 4][n0 + lr]);
            }
            #pragma unroll
            for (int mi = 0; mi < 4; mi++)
                #pragma unroll
                for (int ni = 0; ni < 4; ni++)
                    mma_tf32(acc[mi][ni], a[mi], b[ni]);
        }
    }

    #pragma unroll
    for (int mi = 0; mi < 4; mi++) {
        #pragma unroll
        for (int ni = 0; ni < 4; ni++) {
            int r = row0 + wm*64 + mi*16 + lr;
            int c = col0 + wn*32 + ni*8 + 2*lc;
            float v00 = acc[mi][ni][0] + bias[c];
            float v01 = acc[mi][ni][1] + bias[c+1];
            float v10 = acc[mi][ni][2] + bias[c];
            float v11 = acc[mi][ni][3] + bias[c+1];
            if (MODE == 0) {
                C[r*N + c] = v00;        C[r*N + c + 1] = v01;
                C[(r+8)*N + c] = v10;    C[(r+8)*N + c + 1] = v11;
            } else if (MODE == 1) {
                C[r*N + c] = to_tf32f(v00);        C[r*N + c + 1] = to_tf32f(v01);
                C[(r+8)*N + c] = to_tf32f(v10);    C[(r+8)*N + c + 1] = to_tf32f(v11);
            } else {
                C[r*N + c] = to_tf32f(v00 * QSCALE);        C[r*N + c + 1] = to_tf32f(v01 * QSCALE);
                C[(r+8)*N + c] = to_tf32f(v10 * QSCALE);    C[(r+8)*N + c + 1] = to_tf32f(v11 * QSCALE);
            }
        }
    }
}

template<int MODE>
__global__ __launch_bounds__(256) void gemm_tf32(
    const float* __restrict__ A, const float* __restrict__ B,
    const float* __restrict__ bias, float* __restrict__ C,
    int N, int K)
{
    gemm_body<MODE>(A, B, bias, C, N, K, blockIdx.y * 128, blockIdx.x * 128);
}

// Fused K+V projection: grid.x 0..3 covers 2x256 cols; <2 -> K, >=2 -> V.
__global__ __launch_bounds__(256) void gemm_kv(
    const float* __restrict__ A,
    const float* __restrict__ Wk, const float* __restrict__ bk,
    const float* __restrict__ Wv, const float* __restrict__ bv,
    int K)
{
    int bx = blockIdx.x;
    const float* B; const float* bias; float* C;
    if (bx < 2) { B = Wk; bias = bk; C = g_K; }
    else        { B = Wv; bias = bv; C = g_V; bx -= 2; }
    gemm_body<1>(A, B, bias, C, KV_DIM, K, blockIdx.y * 128, bx * 128);
}

// ---------------------------------------------------------------------------
// Flash attention, tf32 mma, no online softmax.  Cross-tile exp pipelining:
// iteration i computes S_i, exps it (MUFU latency hidden under the PV_{i-1}
// mma stream), runs PV_{i-1} from double-buffered Ps, stages P_i, then
// prefetches tile i+1.  Accumulation order identical to the R8/R12 kernel.
// grid = (64 q-tiles, 16 heads), 128 threads = 4 warps; warp owns 16 q-rows.
// Dynamic smem: Ks 2x32x68 | Vs 2x32x72 | Ps 2x64x36  (54272 B, 4 CTAs/SM).
// ---------------------------------------------------------------------------
#define NTILES (L_SEQ / 32)

__global__ __launch_bounds__(128, 4) void gqa_attn_tf32()
{
    extern __shared__ char sm[];
    auto Ks = reinterpret_cast<float(*)[32][68]>(sm);
    auto Vs = reinterpret_cast<float(*)[32][72]>(sm + 2*32*68*4);
    auto Ps = reinterpret_cast<float(*)[64][36]>(sm + 2*32*68*4 + 2*32*72*4);

    const int head = blockIdx.y, kvh = head >> 2;
    const int q0 = blockIdx.x * 64;
    const int tid = threadIdx.x;
    const int lane = tid & 31, wid = tid >> 5;
    const int lr = lane >> 2, lc = lane & 3;
    const int m_base = wid * 16;

    auto load_tile = [&](int k0, int buf) {
        #pragma unroll
        for (int i = 0; i < 4; i++) {
            int u = tid + i * 128;
            int key = u >> 4, o = (u & 15) * 4;
            cp16(&Ks[buf][key][o], &g_K[(k0 + key) * KV_DIM + kvh*HD + o]);
            cp16(&Vs[buf][key][o], &g_V[(k0 + key) * KV_DIM + kvh*HD + o]);
        }
    };

    // Q fragments (pre-scaled by QSCALE, pre-rounded)
    uint32_t qa[8][4];
    {
        const float* Qb = g_Q + (q0 + m_base) * D_MODEL + head * HD;
        #pragma unroll
        for (int ks = 0; ks < 8; ks++) {
            qa[ks][0] = __float_as_uint(Qb[(lr    )*D_MODEL + ks*8 + lc    ]);
            qa[ks][1] = __float_as_uint(Qb[(lr + 8)*D_MODEL + ks*8 + lc    ]);
            qa[ks][2] = __float_as_uint(Qb[(lr    )*D_MODEL + ks*8 + lc + 4]);
            qa[ks][3] = __float_as_uint(Qb[(lr + 8)*D_MODEL + ks*8 + lc + 4]);
        }
    }

    float o[8][4] = {};         // persistent PV accumulators (never rescaled)
    float lacc0 = 0.f, lacc1 = 0.f;

    load_tile(0, 0);
    CP_COMMIT();

    for (int i = 0; i < NTILES; i++) {
        const int b = i & 1;    // tile i in buf b; P_i staged to Ps[b]
        CP_WAIT0();
        __syncthreads();        // tile i visible to all warps

        // S_i = Q @ K_i^T  (16 x 32 per warp)
        float s[4][4] = {};
        #pragma unroll
        for (int ks = 0; ks < 8; ks++) {
            uint32_t bb[4][2];
            #pragma unroll
            for (int nt = 0; nt < 4; nt++) {
                bb[nt][0] = __float_as_uint(Ks[b][nt*8 + lr][ks*8 + lc    ]);
                bb[nt][1] = __float_as_uint(Ks[b][nt*8 + lr][ks*8 + lc + 4]);
            }
            #pragma unroll
            for (int nt = 0; nt < 4; nt++)
                mma_tf32(s[nt], qa[ks], bb[nt]);
        }

        // exp in place (MUFU results consumed only by the STS below,
        // which sits after the PV_{i-1} mma stream -> latency hidden)
        #pragma unroll
        for (int nt = 0; nt < 4; nt++) {
            s[nt][0] = ex2(s[nt][0]);
            s[nt][1] = ex2(s[nt][1]);
            s[nt][2] = ex2(s[nt][2]);
            s[nt][3] = ex2(s[nt][3]);
            lacc0 += s[nt][0] + s[nt][1];
            lacc1 += s[nt][2] + s[nt][3];
        }

        // PV_{i-1}: o += P_{i-1} @ V_{i-1}  (buffers b^1)
        if (i > 0) {
            #pragma unroll
            for (int ks = 0; ks < 4; ks++) {
                uint32_t a[4];
                a[0] = __float_as_uint(Ps[b^1][m_base + lr    ][ks*8 + lc    ]);
                a[1] = __float_as_uint(Ps[b^1][m_base + lr + 8][ks*8 + lc    ]);
                a[2] = __float_as_uint(Ps[b^1][m_base + lr    ][ks*8 + lc + 4]);
                a[3] = __float_as_uint(Ps[b^1][m_base + lr + 8][ks*8 + lc + 4]);
                #pragma unroll
                for (int nt = 0; nt < 8; nt++) {
                    uint32_t bb[2];
                    bb[0] = __float_as_uint(Vs[b^1][ks*8 + lc    ][nt*8 + lr]);
                    bb[1] = __float_as_uint(Vs[b^1][ks*8 + lc + 4][nt*8 + lr]);
                    mma_tf32(o[nt], a, bb);
                }
            }
        }

        // stage P_i (own rows; read next iteration by this warp only)
        #pragma unroll
        for (int nt = 0; nt < 4; nt++) {
            *(float2*)&Ps[b][m_base + lr    ][nt*8 + 2*lc] = make_float2(s[nt][0], s[nt][1]);
            *(float2*)&Ps[b][m_base + lr + 8][nt*8 + 2*lc] = make_float2(s[nt][2], s[nt][3]);
        }

        __syncthreads();        // all reads of buf b^1 complete
        if (i + 1 < NTILES) load_tile((i + 1) * 32, b ^ 1);
        CP_COMMIT();
    }

    // tail: PV for the last tile (i = NTILES-1, buffers 1)
    {
        #pragma unroll
        for (int ks = 0; ks < 4; ks++) {
            uint32_t a[4];
            a[0] = __float_as_uint(Ps[1][m_base + lr    ][ks*8 + lc    ]);
            a[1] = __float_as_uint(Ps[1][m_base + lr + 8][ks*8 + lc    ]);
            a[2] = __float_as_uint(Ps[1][m_base + lr    ][ks*8 + lc + 4]);
            a[3] = __float_as_uint(Ps[1][m_base + lr + 8][ks*8 + lc + 4]);
            #pragma unroll
            for (int nt = 0; nt < 8; nt++) {
                uint32_t bb[2];
                bb[0] = __float_as_uint(Vs[1][ks*8 + lc    ][nt*8 + lr]);
                bb[1] = __float_as_uint(Vs[1][ks*8 + lc + 4][nt*8 + lr]);
                mma_tf32(o[nt], a, bb);
            }
        }
    }

    // Reduce l across the 4 lanes of each row, normalize, write out
    lacc0 += __shfl_xor_sync(~0u, lacc0, 1); lacc0 += __shfl_xor_sync(~0u, lacc0, 2);
    lacc1 += __shfl_xor_sync(~0u, lacc1, 1); lacc1 += __shfl_xor_sync(~0u, lacc1, 2);
    float inv0 = 1.f / lacc0, inv1 = 1.f / lacc1;
    float* Ob = g_A + (q0 + m_base) * D_MODEL + head * HD;
    #pragma unroll
    for (int nt = 0; nt < 8; nt++) {
        Ob[(lr    )*D_MODEL + nt*8 + 2*lc    ] = to_tf32f(o[nt][0] * inv0);
        Ob[(lr    )*D_MODEL + nt*8 + 2*lc + 1] = to_tf32f(o[nt][1] * inv0);
        Ob[(lr + 8)*D_MODEL + nt*8 + 2*lc    ] = to_tf32f(o[nt][2] * inv1);
        Ob[(lr + 8)*D_MODEL + nt*8 + 2*lc + 1] = to_tf32f(o[nt][3] * inv1);
    }
}

// ---------------------------------------------------------------------------
extern "C" void kernel_launch(void* const* d_in, const int* in_sizes, int n_in,
                              void* d_out, int out_size)
{
    const float* x  = (const float*)d_in[0];
    const float* Wq = (const float*)d_in[1];
    const float* bq = (const float*)d_in[2];
    const float* Wk = (const float*)d_in[3];
    const float* bk = (const float*)d_in[4];
    const float* Wv = (const float*)d_in[5];
    const float* bv = (const float*)d_in[6];
    const float* Wo = (const float*)d_in[7];
    const float* bo = (const float*)d_in[8];
    float* out = (float*)d_out;

    float *X32, *Wq32, *Wk32, *Wv32, *Wo32, *Qp, *Ap;
    cudaGetSymbolAddress((void**)&X32,  g_X32);
    cudaGetSymbolAddress((void**)&Wq32, g_Wq32);
    cudaGetSymbolAddress((void**)&Wk32, g_Wk32);
    cudaGetSymbolAddress((void**)&Wv32, g_Wv32);
    cudaGetSymbolAddress((void**)&Wo32, g_Wo32);
    cudaGetSymbolAddress((void**)&Qp,   g_Q);
    cudaGetSymbolAddress((void**)&Ap,   g_A);

    // Opt in to >48KB dynamic shared memory (idempotent, host-side)
    cudaFuncSetAttribute(gemm_tf32<0>, cudaFuncAttributeMaxDynamicSharedMemorySize, GEMM_SMEM_BYTES);
    cudaFuncSetAttribute(gemm_tf32<2>, cudaFuncAttributeMaxDynamicSharedMemorySize, GEMM_SMEM_BYTES);
    cudaFuncSetAttribute(gemm_kv,      cudaFuncAttributeMaxDynamicSharedMemorySize, GEMM_SMEM_BYTES);
    cudaFuncSetAttribute(gqa_attn_tf32, cudaFuncAttributeMaxDynamicSharedMemorySize, ATTN_SMEM_BYTES);

    // Prep: one fused tf32-rounding pass
    prep_round_all<<<(PREP_TOTAL + 255)/256, 256>>>(x, Wq, Wk, Wv, Wo);

    // Projections
    gemm_tf32<2><<<dim3(D_MODEL/128, L_SEQ/128), 256, GEMM_SMEM_BYTES>>>(X32, Wq32, bq, Qp, D_MODEL, D_MODEL);
    gemm_kv    <<<dim3(4,            L_SEQ/128), 256, GEMM_SMEM_BYTES>>>(X32, Wk32, bk, Wv32, bv, D_MODEL);
    // Attention (exp-pipelined)
    gqa_attn_tf32<<<dim3(L_SEQ/64, NHEADS), 128, ATTN_SMEM_BYTES>>>();
    // Output projection
    gemm_tf32<0><<<dim3(D_MODEL/128, L_SEQ/128), 256, GEMM_SMEM_BYTES>>>(Ap, Wo32, bo, out, D_MODEL, D_MODEL);
}

// round 17
// speedup vs baseline: 1.0010x; 1.0001x over previous
#include <cuda_runtime.h>
#include <cstdint>

#define D_MODEL 1024
#define KV_DIM  256
#define L_SEQ   4096
#define HD      64
#define NHEADS  16

// Scratch (device globals; no allocations allowed)
__device__ float g_X32 [L_SEQ * D_MODEL];
__device__ float g_Wq32[D_MODEL * D_MODEL];
__device__ float g_Wk32[D_MODEL * KV_DIM];
__device__ float g_Wv32[D_MODEL * KV_DIM];
__device__ float g_Wo32[D_MODEL * D_MODEL];
__device__ float g_Q [L_SEQ * D_MODEL];   // rounded + pre-scaled by QSCALE
__device__ float g_K [L_SEQ * KV_DIM];    // rounded, row-major
__device__ float g_V [L_SEQ * KV_DIM];    // rounded
__device__ float g_A [L_SEQ * D_MODEL];   // attention out, rounded

// 0.125 * log2(e): folds 1/sqrt(64) AND exp->exp2
#define QSCALE 0.18033688011112042f

__device__ __forceinline__ uint32_t to_tf32(float x) {
    uint32_t y;
    asm("cvt.rna.tf32.f32 %0, %1;" : "=r"(y) : "f"(x));
    return y;
}
__device__ __forceinline__ float to_tf32f(float x) { return __uint_as_float(to_tf32(x)); }

__device__ __forceinline__ float ex2(float x) {
    float y;
    asm("ex2.approx.f32 %0, %1;" : "=f"(y) : "f"(x));
    return y;
}

__device__ __forceinline__ void mma_tf32(float c[4], const uint32_t a[4], const uint32_t b[2]) {
    asm volatile("mma.sync.aligned.m16n8k8.row.col.f32.tf32.tf32.f32 "
        "{%0,%1,%2,%3},{%4,%5,%6,%7},{%8,%9},{%0,%1,%2,%3};"
        : "+f"(c[0]), "+f"(c[1]), "+f"(c[2]), "+f"(c[3])
        : "r"(a[0]), "r"(a[1]), "r"(a[2]), "r"(a[3]), "r"(b[0]), "r"(b[1]));
}

__device__ __forceinline__ void cp16(void* smem, const void* gmem) {
    uint32_t s = (uint32_t)__cvta_generic_to_shared(smem);
    asm volatile("cp.async.cg.shared.global [%0], [%1], 16;" :: "r"(s), "l"(gmem));
}
#define CP_COMMIT() asm volatile("cp.async.commit_group;")
#define CP_WAIT1()  asm volatile("cp.async.wait_group 1;")
#define CP_WAIT0()  asm volatile("cp.async.wait_group 0;")

// Dynamic smem sizes
#define GEMM_SMEM_BYTES  (3 * (128*20 + 16*136) * 4)            // 56832
#define ATTN_SMEM_BYTES  ((2*32*68 + 2*32*72 + 2*64*36) * 4)    // 54272

// ---------------------------------------------------------------------------
// Fused prep: tf32-round x, Wq, Wk, Wv, Wo
// ---------------------------------------------------------------------------
#define SEG_X  (L_SEQ*D_MODEL/4)
#define SEG_WQ (D_MODEL*D_MODEL/4)
#define SEG_WK (D_MODEL*KV_DIM/4)
#define PREP_TOTAL (SEG_X + 2*SEG_WQ + 2*SEG_WK)

__global__ __launch_bounds__(256) void prep_round_all(
    const float* __restrict__ x,  const float* __restrict__ Wq,
    const float* __restrict__ Wk, const float* __restrict__ Wv,
    const float* __restrict__ Wo)
{
    int i = blockIdx.x * blockDim.x + threadIdx.x;
    if (i >= PREP_TOTAL) return;
    const float* src; float* dst; int off;
    if (i < SEG_X)                         { src = x;  dst = g_X32;  off = i; }
    else if (i < SEG_X + SEG_WQ)           { src = Wq; dst = g_Wq32; off = i - SEG_X; }
    else if (i < SEG_X + SEG_WQ + SEG_WK)  { src = Wk; dst = g_Wk32; off = i - SEG_X - SEG_WQ; }
    else if (i < SEG_X + SEG_WQ + 2*SEG_WK){ src = Wv; dst = g_Wv32; off = i - SEG_X - SEG_WQ - SEG_WK; }
    else                                   { src = Wo; dst = g_Wo32; off = i - SEG_X - SEG_WQ - 2*SEG_WK; }
    float4 v = ((const float4*)src)[off];
    v.x = to_tf32f(v.x); v.y = to_tf32f(v.y);
    v.z = to_tf32f(v.z); v.w = to_tf32f(v.w);
    ((float4*)dst)[off] = v;
}

// ---------------------------------------------------------------------------
// tf32 GEMM. Block 128x128, 256 thr = 8 warps (2m x 4n), warp tile 64x32.
// 3-stage cp.async pipeline (dynamic smem), ONE barrier per k-step.
// MODE: 0 plain out; 1 rounded; 2 rounded*QSCALE (for Q).
// ---------------------------------------------------------------------------
template<int MODE>
__device__ __forceinline__ void gemm_body(
    const float* __restrict__ A, const float* __restrict__ B,
    const float* __restrict__ bias, float* __restrict__ C,
    int N, int K, int row0, int col0)
{
    extern __shared__ char sm[];
    auto As = reinterpret_cast<float(*)[128][20]>(sm);
    auto Bs = reinterpret_cast<float(*)[16][136]>(sm + 3 * 128 * 20 * 4);

    const int tid = threadIdx.x;
    const int lane = tid & 31, wid = tid >> 5;
    const int wm = wid >> 2, wn = wid & 3;
    const int lr = lane >> 2, lc = lane & 3;

    auto load_stage = [&](int buf, int k0) {
        #pragma unroll
        for (int i = 0; i < 2; i++) {               // A: 128 rows x 4 float4
            int u = tid + i * 256;
            int r = u >> 2, o = (u & 3) * 4;
            cp16(&As[buf][r][o], &A[(row0 + r) * K + k0 + o]);
        }
        #pragma unroll
        for (int i = 0; i < 2; i++) {               // B: 16 rows x 32 float4
            int u = tid + i * 256;
            int kk = u >> 5, o = (u & 31) * 4;
            cp16(&Bs[buf][kk][o], &B[(k0 + kk) * N + col0 + o]);
        }
    };

    const int NT = K / 16;
    float acc[4][4][4] = {};
    load_stage(0, 0);  CP_COMMIT();
    load_stage(1, 16); CP_COMMIT();

    for (int t = 0; t < NT; t++) {
        int buf = t % 3;
        CP_WAIT1();            // group t landed (t+1 may be in flight)
        __syncthreads();       // also protects buf (t+2)%3 from early overwrite
        if (t + 2 < NT) load_stage((t + 2) % 3, (t + 2) * 16);
        CP_COMMIT();           // always commit -> uniform group FIFO

        #pragma unroll
        for (int ks = 0; ks < 2; ks++) {
            uint32_t a[4][4], b[4][2];
            #pragma unroll
            for (int mi = 0; mi < 4; mi++) {
                int m0 = wm * 64 + mi * 16;
                a[mi][0] = __float_as_uint(As[buf][m0 + lr    ][ks*8 + lc    ]);
                a[mi][1] = __float_as_uint(As[buf][m0 + lr + 8][ks*8 + lc    ]);
                a[mi][2] = __float_as_uint(As[buf][m0 + lr    ][ks*8 + lc + 4]);
                a[mi][3] = __float_as_uint(As[buf][m0 + lr + 8][ks*8 + lc + 4]);
            }
            #pragma unroll
            for (int ni = 0; ni < 4; ni++) {
                int n0 = wn * 32 + ni * 8;
                b[ni][0] = __float_as_uint(Bs[buf][ks*8 + lc    ][n0 + lr]);
                b[ni][1] = __float_as_uint(Bs[buf][ks*8 + lc + 4][n0 + lr]);
            }
            #pragma unroll
            for (int mi = 0; mi < 4; mi++)
                #pragma unroll
                for (int ni = 0; ni < 4; ni++)
                    mma_tf32(acc[mi][ni], a[mi], b[ni]);
        }
    }

    #pragma unroll
    for (int mi = 0; mi < 4; mi++) {
        #pragma unroll
        for (int ni = 0; ni < 4; ni++) {
            int r = row0 + wm*64 + mi*16 + lr;
            int c = col0 + wn*32 + ni*8 + 2*lc;
            float v00 = acc[mi][ni][0] + bias[c];
            float v01 = acc[mi][ni][1] + bias[c+1];
            float v10 = acc[mi][ni][2] + bias[c];
            float v11 = acc[mi][ni][3] + bias[c+1];
            if (MODE == 0) {
                C[r*N + c] = v00;        C[r*N + c + 1] = v01;
                C[(r+8)*N + c] = v10;    C[(r+8)*N + c + 1] = v11;
            } else if (MODE == 1) {
                C[r*N + c] = to_tf32f(v00);        C[r*N + c + 1] = to_tf32f(v01);
                C[(r+8)*N + c] = to_tf32f(v10);    C[(r+8)*N + c + 1] = to_tf32f(v11);
            } else {
                C[r*N + c] = to_tf32f(v00 * QSCALE);        C[r*N + c + 1] = to_tf32f(v01 * QSCALE);
                C[(r+8)*N + c] = to_tf32f(v10 * QSCALE);    C[(r+8)*N + c + 1] = to_tf32f(v11 * QSCALE);
            }
        }
    }
}

template<int MODE>
__global__ __launch_bounds__(256) void gemm_tf32(
    const float* __restrict__ A, const float* __restrict__ B,
    const float* __restrict__ bias, float* __restrict__ C,
    int N, int K)
{
    gemm_body<MODE>(A, B, bias, C, N, K, blockIdx.y * 128, blockIdx.x * 128);
}

// Fused K+V projection: grid.x 0..3 covers 2x256 cols; <2 -> K, >=2 -> V.
__global__ __launch_bounds__(256) void gemm_kv(
    const float* __restrict__ A,
    const float* __restrict__ Wk, const float* __restrict__ bk,
    const float* __restrict__ Wv, const float* __restrict__ bv,
    int K)
{
    int bx = blockIdx.x;
    const float* B; const float* bias; float* C;
    if (bx < 2) { B = Wk; bias = bk; C = g_K; }
    else        { B = Wv; bias = bv; C = g_V; bx -= 2; }
    gemm_body<1>(A, B, bias, C, KV_DIM, K, blockIdx.y * 128, bx * 128);
}

// ---------------------------------------------------------------------------
// Flash attention, tf32 mma, no online softmax.  Cross-tile exp pipelining:
// iteration i computes S_i, exps it (MUFU latency hidden under the PV_{i-1}
// mma stream), runs PV_{i-1} from double-buffered Ps, stages P_i, then
// prefetches tile i+1.  Accumulation order identical to the R8/R12 kernel.
// grid = (64 q-tiles, 16 heads), 128 threads = 4 warps; warp owns 16 q-rows.
// Dynamic smem: Ks 2x32x68 | Vs 2x32x72 | Ps 2x64x36  (54272 B, 4 CTAs/SM).
// ---------------------------------------------------------------------------
#define NTILES (L_SEQ / 32)

__global__ __launch_bounds__(128, 4) void gqa_attn_tf32()
{
    extern __shared__ char sm[];
    auto Ks = reinterpret_cast<float(*)[32][68]>(sm);
    auto Vs = reinterpret_cast<float(*)[32][72]>(sm + 2*32*68*4);
    auto Ps = reinterpret_cast<float(*)[64][36]>(sm + 2*32*68*4 + 2*32*72*4);

    const int head = blockIdx.y, kvh = head >> 2;
    const int q0 = blockIdx.x * 64;
    const int tid = threadIdx.x;
    const int lane = tid & 31, wid = tid >> 5;
    const int lr = lane >> 2, lc = lane & 3;
    const int m_base = wid * 16;

    auto load_tile = [&](int k0, int buf) {
        #pragma unroll
        for (int i = 0; i < 4; i++) {
            int u = tid + i * 128;
            int key = u >> 4, o = (u & 15) * 4;
            cp16(&Ks[buf][key][o], &g_K[(k0 + key) * KV_DIM + kvh*HD + o]);
            cp16(&Vs[buf][key][o], &g_V[(k0 + key) * KV_DIM + kvh*HD + o]);
        }
    };

    // Q fragments (pre-scaled by QSCALE, pre-rounded)
    uint32_t qa[8][4];
    {
        const float* Qb = g_Q + (q0 + m_base) * D_MODEL + head * HD;
        #pragma unroll
        for (int ks = 0; ks < 8; ks++) {
            qa[ks][0] = __float_as_uint(Qb[(lr    )*D_MODEL + ks*8 + lc    ]);
            qa[ks][1] = __float_as_uint(Qb[(lr + 8)*D_MODEL + ks*8 + lc    ]);
            qa[ks][2] = __float_as_uint(Qb[(lr    )*D_MODEL + ks*8 + lc + 4]);
            qa[ks][3] = __float_as_uint(Qb[(lr + 8)*D_MODEL + ks*8 + lc + 4]);
        }
    }

    float o[8][4] = {};         // persistent PV accumulators (never rescaled)
    float lacc0 = 0.f, lacc1 = 0.f;

    load_tile(0, 0);
    CP_COMMIT();

    for (int i = 0; i < NTILES; i++) {
        const int b = i & 1;    // tile i in buf b; P_i staged to Ps[b]
        CP_WAIT0();
        __syncthreads();        // tile i visible to all warps

        // S_i = Q @ K_i^T  (16 x 32 per warp)
        float s[4][4] = {};
        #pragma unroll
        for (int ks = 0; ks < 8; ks++) {
            uint32_t bb[4][2];
            #pragma unroll
            for (int nt = 0; nt < 4; nt++) {
                bb[nt][0] = __float_as_uint(Ks[b][nt*8 + lr][ks*8 + lc    ]);
                bb[nt][1] = __float_as_uint(Ks[b][nt*8 + lr][ks*8 + lc + 4]);
            }
            #pragma unroll
            for (int nt = 0; nt < 4; nt++)
                mma_tf32(s[nt], qa[ks], bb[nt]);
        }

        // exp in place (MUFU results consumed only by the STS below,
        // which sits after the PV_{i-1} mma stream -> latency hidden)
        #pragma unroll
        for (int nt = 0; nt < 4; nt++) {
            s[nt][0] = ex2(s[nt][0]);
            s[nt][1] = ex2(s[nt][1]);
            s[nt][2] = ex2(s[nt][2]);
            s[nt][3] = ex2(s[nt][3]);
            lacc0 += s[nt][0] + s[nt][1];
            lacc1 += s[nt][2] + s[nt][3];
        }

        // PV_{i-1}: o += P_{i-1} @ V_{i-1}  (buffers b^1)
        if (i > 0) {
            #pragma unroll
            for (int ks = 0; ks < 4; ks++) {
                uint32_t a[4];
                a[0] = __float_as_uint(Ps[b^1][m_base + lr    ][ks*8 + lc    ]);
                a[1] = __float_as_uint(Ps[b^1][m_base + lr + 8][ks*8 + lc    ]);
                a[2] = __float_as_uint(Ps[b^1][m_base + lr    ][ks*8 + lc + 4]);
                a[3] = __float_as_uint(Ps[b^1][m_base + lr + 8][ks*8 + lc + 4]);
                #pragma unroll
                for (int nt = 0; nt < 8; nt++) {
                    uint32_t bb[2];
                    bb[0] = __float_as_uint(Vs[b^1][ks*8 + lc    ][nt*8 + lr]);
                    bb[1] = __float_as_uint(Vs[b^1][ks*8 + lc + 4][nt*8 + lr]);
                    mma_tf32(o[nt], a, bb);
                }
            }
        }

        // stage P_i (own rows; read next iteration by this warp only)
        #pragma unroll
        for (int nt = 0; nt < 4; nt++) {
            *(float2*)&Ps[b][m_base + lr    ][nt*8 + 2*lc] = make_float2(s[nt][0], s[nt][1]);
            *(float2*)&Ps[b][m_base + lr + 8][nt*8 + 2*lc] = make_float2(s[nt][2], s[nt][3]);
        }

        __syncthreads();        // all reads of buf b^1 complete
        if (i + 1 < NTILES) load_tile((i + 1) * 32, b ^ 1);
        CP_COMMIT();
    }

    // tail: PV for the last tile (i = NTILES-1, buffers 1)
    {
        #pragma unroll
        for (int ks = 0; ks < 4; ks++) {
            uint32_t a[4];
            a[0] = __float_as_uint(Ps[1][m_base + lr    ][ks*8 + lc    ]);
            a[1] = __float_as_uint(Ps[1][m_base + lr + 8][ks*8 + lc    ]);
            a[2] = __float_as_uint(Ps[1][m_base + lr    ][ks*8 + lc + 4]);
            a[3] = __float_as_uint(Ps[1][m_base + lr + 8][ks*8 + lc + 4]);
            #pragma unroll
            for (int nt = 0; nt < 8; nt++) {
                uint32_t bb[2];
                bb[0] = __float_as_uint(Vs[1][ks*8 + lc    ][nt*8 + lr]);
                bb[1] = __float_as_uint(Vs[1][ks*8 + lc + 4][nt*8 + lr]);
                mma_tf32(o[nt], a, bb);
            }
        }
    }

    // Reduce l across the 4 lanes of each row, normalize, write out
    lacc0 += __shfl_xor_sync(~0u, lacc0, 1); lacc0 += __shfl_xor_sync(~0u, lacc0, 2);
    lacc1 += __shfl_xor_sync(~0u, lacc1, 1); lacc1 += __shfl_xor_sync(~0u, lacc1, 2);
    float inv0 = 1.f / lacc0, inv1 = 1.f / lacc1;
    float* Ob = g_A + (q0 + m_base) * D_MODEL + head * HD;
    #pragma unroll
    for (int nt = 0; nt < 8; nt++) {
        Ob[(lr    )*D_MODEL + nt*8 + 2*lc    ] = to_tf32f(o[nt][0] * inv0);
        Ob[(lr    )*D_MODEL + nt*8 + 2*lc + 1] = to_tf32f(o[nt][1] * inv0);
        Ob[(lr + 8)*D_MODEL + nt*8 + 2*lc    ] = to_tf32f(o[nt][2] * inv1);
        Ob[(lr + 8)*D_MODEL + nt*8 + 2*lc + 1] = to_tf32f(o[nt][3] * inv1);
    }
}

// ---------------------------------------------------------------------------
extern "C" void kernel_launch(void* const* d_in, const int* in_sizes, int n_in,
                              void* d_out, int out_size)
{
    const float* x  = (const float*)d_in[0];
    const float* Wq = (const float*)d_in[1];
    const float* bq = (const float*)d_in[2];
    const float* Wk = (const float*)d_in[3];
    const float* bk = (const float*)d_in[4];
    const float* Wv = (const float*)d_in[5];
    const float* bv = (const float*)d_in[6];
    const float* Wo = (const float*)d_in[7];
    const float* bo = (const float*)d_in[8];
    float* out = (float*)d_out;

    float *X32, *Wq32, *Wk32, *Wv32, *Wo32, *Qp, *Ap;
    cudaGetSymbolAddress((void**)&X32,  g_X32);
    cudaGetSymbolAddress((void**)&Wq32, g_Wq32);
    cudaGetSymbolAddress((void**)&Wk32, g_Wk32);
    cudaGetSymbolAddress((void**)&Wv32, g_Wv32);
    cudaGetSymbolAddress((void**)&Wo32, g_Wo32);
    cudaGetSymbolAddress((void**)&Qp,   g_Q);
    cudaGetSymbolAddress((void**)&Ap,   g_A);

    // Opt in to >48KB dynamic shared memory (idempotent, host-side)
    cudaFuncSetAttribute(gemm_tf32<0>, cudaFuncAttributeMaxDynamicSharedMemorySize, GEMM_SMEM_BYTES);
    cudaFuncSetAttribute(gemm_tf32<2>, cudaFuncAttributeMaxDynamicSharedMemorySize, GEMM_SMEM_BYTES);
    cudaFuncSetAttribute(gemm_kv,      cudaFuncAttributeMaxDynamicSharedMemorySize, GEMM_SMEM_BYTES);
    cudaFuncSetAttribute(gqa_attn_tf32, cudaFuncAttributeMaxDynamicSharedMemorySize, ATTN_SMEM_BYTES);

    // Prep: one fused tf32-rounding pass
    prep_round_all<<<(PREP_TOTAL + 255)/256, 256>>>(x, Wq, Wk, Wv, Wo);

    // Projections
    gemm_tf32<2><<<dim3(D_MODEL/128, L_SEQ/128), 256, GEMM_SMEM_BYTES>>>(X32, Wq32, bq, Qp, D_MODEL, D_MODEL);
    gemm_kv    <<<dim3(4,            L_SEQ/128), 256, GEMM_SMEM_BYTES>>>(X32, Wk32, bk, Wv32, bv, D_MODEL);
    // Attention (exp-pipelined)
    gqa_attn_tf32<<<dim3(L_SEQ/64, NHEADS), 128, ATTN_SMEM_BYTES>>>();
    // Output projection
    gemm_tf32<0><<<dim3(D_MODEL/128, L_SEQ/128), 256, GEMM_SMEM_BYTES>>>(Ap, Wo32, bo, out, D_MODEL, D_MODEL);
}